// round 1
// baseline (speedup 1.0000x reference)
#include <cuda_runtime.h>
#include <math.h>

#define T_TOK 8192
#define D_IN  512
#define H_HID 1024
#define NE    16
#define TOPK  2
#define NA    (T_TOK * TOPK)   // 16384 assignments

#define BM 64
#define BN 64
#define BK 16
#define MAX_TILES (NA / BM + NE)   // 272

// ---------------- scratch (device globals: no allocations allowed) ----------
__device__ float g_h[(size_t)NA * H_HID];   // GEMM1 output (post-GELU)
__device__ float g_o[(size_t)NA * D_IN];    // GEMM2 output (per-assignment)
__device__ int   g_counts[NE];
__device__ int   g_cursor[NE];
__device__ int   g_offsets[NE + 1];
__device__ int   g_bucket_tok[NA];
__device__ int   g_tok_pos[NA];             // router: expert idx -> scatter: bucket pos
__device__ float g_tok_w[NA];
__device__ int2  g_tiles[MAX_TILES];
__device__ int   g_ntiles;

// ---------------- helpers ----------------------------------------------------
__device__ __forceinline__ float gelu_exact(float v) {
    return 0.5f * v * (1.0f + erff(v * 0.70710678118654752f));
}

// ---------------- 0: zero counters -------------------------------------------
__global__ void zero_kernel() {
    int i = threadIdx.x;
    if (i < NE) { g_counts[i] = 0; g_cursor[i] = 0; }
}

// ---------------- 1: router (one warp per token) -----------------------------
__global__ void router_kernel(const float* __restrict__ x,
                              const float* __restrict__ Wr,
                              const float* __restrict__ br) {
    int warp = (blockIdx.x * blockDim.x + threadIdx.x) >> 5;
    int lane = threadIdx.x & 31;
    if (warp >= T_TOK) return;

    const float* xr = x + (size_t)warp * D_IN;
    float acc[NE];
#pragma unroll
    for (int e = 0; e < NE; e++) acc[e] = 0.f;

    for (int d = lane; d < D_IN; d += 32) {
        float xv = xr[d];
        const float* wrow = Wr + d * NE;
#pragma unroll
        for (int e = 0; e < NE; e++) acc[e] += xv * wrow[e];
    }
#pragma unroll
    for (int e = 0; e < NE; e++) {
#pragma unroll
        for (int off = 16; off; off >>= 1)
            acc[e] += __shfl_xor_sync(0xffffffffu, acc[e], off);
    }

    if (lane == 0) {
        float lg[NE];
        float mx = -1e30f;
#pragma unroll
        for (int e = 0; e < NE; e++) { lg[e] = acc[e] + br[e]; mx = fmaxf(mx, lg[e]); }
        float sum = 0.f;
#pragma unroll
        for (int e = 0; e < NE; e++) { lg[e] = expf(lg[e] - mx); sum += lg[e]; }
        (void)sum; // top-2 normalization cancels the softmax denominator

        int   i0 = 0; float p0 = lg[0];
#pragma unroll
        for (int e = 1; e < NE; e++) if (lg[e] > p0) { p0 = lg[e]; i0 = e; }
        int   i1 = -1; float p1 = -1.f;
#pragma unroll
        for (int e = 0; e < NE; e++) if (e != i0 && lg[e] > p1) { p1 = lg[e]; i1 = e; }

        float inv = 1.f / (p0 + p1);
        g_tok_w[warp * 2 + 0] = p0 * inv;
        g_tok_w[warp * 2 + 1] = p1 * inv;
        g_tok_pos[warp * 2 + 0] = i0;   // expert idx for now
        g_tok_pos[warp * 2 + 1] = i1;
        atomicAdd(&g_counts[i0], 1);
        atomicAdd(&g_counts[i1], 1);
    }
}

// ---------------- 2: scan + tile worklist ------------------------------------
__global__ void scan_kernel() {
    if (threadIdx.x != 0) return;
    int off = 0;
    for (int e = 0; e < NE; e++) { g_offsets[e] = off; off += g_counts[e]; }
    g_offsets[NE] = off;
    int nt = 0;
    for (int e = 0; e < NE; e++)
        for (int r = 0; r < g_counts[e]; r += BM)
            g_tiles[nt++] = make_int2(e, g_offsets[e] + r);
    g_ntiles = nt;
}

// ---------------- 3: scatter assignments into expert buckets -----------------
__global__ void scatter_kernel() {
    int i = blockIdx.x * blockDim.x + threadIdx.x;
    if (i >= NA) return;
    int e   = g_tok_pos[i];
    int pos = g_offsets[e] + atomicAdd(&g_cursor[e], 1);
    g_bucket_tok[pos] = i >> 1;
    g_tok_pos[i]      = pos;
    // weight stays per-token in g_tok_w; combine reads it via g_tok_pos
}

// ---------------- 4: GEMM1  h = gelu(Xg @ W1[e] + b1[e]) ---------------------
__global__ __launch_bounds__(256) void gemm1_kernel(const float* __restrict__ x,
                                                    const float* __restrict__ W1,
                                                    const float* __restrict__ b1) {
    int tile = blockIdx.y;
    if (tile >= g_ntiles) return;
    int e    = g_tiles[tile].x;
    int row0 = g_tiles[tile].y;
    int rows = min(BM, g_offsets[e + 1] - row0);
    int n0   = blockIdx.x * BN;

    const float* B = W1 + (size_t)e * D_IN * H_HID;

    __shared__ float As[BM][BK];
    __shared__ float Bs[BK][BN];
    __shared__ int   s_tok[BM];

    int tid = threadIdx.x;
    if (tid < BM) s_tok[tid] = (tid < rows) ? g_bucket_tok[row0 + tid] : -1;
    __syncthreads();

    int tr = tid >> 4, tc = tid & 15;
    int lm = tid >> 2, lkq = (tid & 3) * 4;   // A loads: row lm, k chunk lkq
    int lk = tid >> 4, ln  = (tid & 15) * 4;  // B loads: k row lk, n chunk ln

    float c[4][4] = {};
    int tok = s_tok[lm];

    for (int k0 = 0; k0 < D_IN; k0 += BK) {
        float4 av = make_float4(0.f, 0.f, 0.f, 0.f);
        if (tok >= 0)
            av = *(const float4*)&x[(size_t)tok * D_IN + k0 + lkq];
        As[lm][lkq + 0] = av.x; As[lm][lkq + 1] = av.y;
        As[lm][lkq + 2] = av.z; As[lm][lkq + 3] = av.w;

        float4 bv = *(const float4*)&B[(size_t)(k0 + lk) * H_HID + n0 + ln];
        *(float4*)&Bs[lk][ln] = bv;
        __syncthreads();

#pragma unroll
        for (int k = 0; k < BK; k++) {
            float a0 = As[tr * 4 + 0][k];
            float a1 = As[tr * 4 + 1][k];
            float a2 = As[tr * 4 + 2][k];
            float a3 = As[tr * 4 + 3][k];
            float4 b = *(const float4*)&Bs[k][tc * 4];
            c[0][0] += a0 * b.x; c[0][1] += a0 * b.y; c[0][2] += a0 * b.z; c[0][3] += a0 * b.w;
            c[1][0] += a1 * b.x; c[1][1] += a1 * b.y; c[1][2] += a1 * b.z; c[1][3] += a1 * b.w;
            c[2][0] += a2 * b.x; c[2][1] += a2 * b.y; c[2][2] += a2 * b.z; c[2][3] += a2 * b.w;
            c[3][0] += a3 * b.x; c[3][1] += a3 * b.y; c[3][2] += a3 * b.z; c[3][3] += a3 * b.w;
        }
        __syncthreads();
    }

    int n = n0 + tc * 4;
    float4 bias = *(const float4*)&b1[(size_t)e * H_HID + n];
#pragma unroll
    for (int i = 0; i < 4; i++) {
        int m = tr * 4 + i;
        if (m < rows) {
            float4 r;
            r.x = gelu_exact(c[i][0] + bias.x);
            r.y = gelu_exact(c[i][1] + bias.y);
            r.z = gelu_exact(c[i][2] + bias.z);
            r.w = gelu_exact(c[i][3] + bias.w);
            *(float4*)&g_h[(size_t)(row0 + m) * H_HID + n] = r;
        }
    }
}

// ---------------- 5: GEMM2  o = h @ W2[e] + b2[e] -----------------------------
__global__ __launch_bounds__(256) void gemm2_kernel(const float* __restrict__ W2,
                                                    const float* __restrict__ b2) {
    int tile = blockIdx.y;
    if (tile >= g_ntiles) return;
    int e    = g_tiles[tile].x;
    int row0 = g_tiles[tile].y;
    int rows = min(BM, g_offsets[e + 1] - row0);
    int n0   = blockIdx.x * BN;

    const float* B = W2 + (size_t)e * H_HID * D_IN;

    __shared__ float As[BM][BK];
    __shared__ float Bs[BK][BN];

    int tid = threadIdx.x;
    int tr = tid >> 4, tc = tid & 15;
    int lm = tid >> 2, lkq = (tid & 3) * 4;
    int lk = tid >> 4, ln  = (tid & 15) * 4;

    float c[4][4] = {};

    for (int k0 = 0; k0 < H_HID; k0 += BK) {
        float4 av = make_float4(0.f, 0.f, 0.f, 0.f);
        if (lm < rows)
            av = *(const float4*)&g_h[(size_t)(row0 + lm) * H_HID + k0 + lkq];
        As[lm][lkq + 0] = av.x; As[lm][lkq + 1] = av.y;
        As[lm][lkq + 2] = av.z; As[lm][lkq + 3] = av.w;

        float4 bv = *(const float4*)&B[(size_t)(k0 + lk) * D_IN + n0 + ln];
        *(float4*)&Bs[lk][ln] = bv;
        __syncthreads();

#pragma unroll
        for (int k = 0; k < BK; k++) {
            float a0 = As[tr * 4 + 0][k];
            float a1 = As[tr * 4 + 1][k];
            float a2 = As[tr * 4 + 2][k];
            float a3 = As[tr * 4 + 3][k];
            float4 b = *(const float4*)&Bs[k][tc * 4];
            c[0][0] += a0 * b.x; c[0][1] += a0 * b.y; c[0][2] += a0 * b.z; c[0][3] += a0 * b.w;
            c[1][0] += a1 * b.x; c[1][1] += a1 * b.y; c[1][2] += a1 * b.z; c[1][3] += a1 * b.w;
            c[2][0] += a2 * b.x; c[2][1] += a2 * b.y; c[2][2] += a2 * b.z; c[2][3] += a2 * b.w;
            c[3][0] += a3 * b.x; c[3][1] += a3 * b.y; c[3][2] += a3 * b.z; c[3][3] += a3 * b.w;
        }
        __syncthreads();
    }

    int n = n0 + tc * 4;
    float4 bias = *(const float4*)&b2[(size_t)e * D_IN + n];
#pragma unroll
    for (int i = 0; i < 4; i++) {
        int m = tr * 4 + i;
        if (m < rows) {
            float4 r;
            r.x = c[i][0] + bias.x;
            r.y = c[i][1] + bias.y;
            r.z = c[i][2] + bias.z;
            r.w = c[i][3] + bias.w;
            *(float4*)&g_o[(size_t)(row0 + m) * D_IN + n] = r;
        }
    }
}

// ---------------- 6: combine + residual (deterministic gather) ---------------
__global__ void combine_kernel(const float* __restrict__ x, float* __restrict__ out) {
    int t = blockIdx.x;
    int d = threadIdx.x * 4;
    float w0 = g_tok_w[2 * t + 0], w1 = g_tok_w[2 * t + 1];
    int   p0 = g_tok_pos[2 * t + 0], p1 = g_tok_pos[2 * t + 1];
    float4 xv = *(const float4*)&x[(size_t)t * D_IN + d];
    float4 o0 = *(const float4*)&g_o[(size_t)p0 * D_IN + d];
    float4 o1 = *(const float4*)&g_o[(size_t)p1 * D_IN + d];
    float4 r;
    r.x = xv.x + w0 * o0.x + w1 * o1.x;
    r.y = xv.y + w0 * o0.y + w1 * o1.y;
    r.z = xv.z + w0 * o0.z + w1 * o1.z;
    r.w = xv.w + w0 * o0.w + w1 * o1.w;
    *(float4*)&out[(size_t)t * D_IN + d] = r;
}

// ---------------- launch ------------------------------------------------------
extern "C" void kernel_launch(void* const* d_in, const int* in_sizes, int n_in,
                              void* d_out, int out_size) {
    const float* x  = (const float*)d_in[0];
    const float* Wr = (const float*)d_in[1];
    const float* br = (const float*)d_in[2];
    const float* W1 = (const float*)d_in[3];
    const float* b1 = (const float*)d_in[4];
    const float* W2 = (const float*)d_in[5];
    const float* b2 = (const float*)d_in[6];
    float* out = (float*)d_out;

    zero_kernel<<<1, 32>>>();
    router_kernel<<<T_TOK / 8, 256>>>(x, Wr, br);   // 8 warps/block, warp per token
    scan_kernel<<<1, 32>>>();
    scatter_kernel<<<(NA + 255) / 256, 256>>>();
    gemm1_kernel<<<dim3(H_HID / BN, MAX_TILES), 256>>>(x, W1, b1);
    gemm2_kernel<<<dim3(D_IN / BN, MAX_TILES), 256>>>(W2, b2);
    combine_kernel<<<T_TOK, 128>>>(x, out);
}

// round 11
// speedup vs baseline: 2.2680x; 2.2680x over previous
#include <cuda_runtime.h>
#include <math.h>
#include <stdint.h>

#define T_TOK 8192
#define D_IN  512
#define H_HID 1024
#define NE    16
#define NA    (T_TOK * 2)          // 16384 assignments

#define BM 128
#define BN 128
#define BK 16
#define MAX_TILES (NA / BM + NE)   // 144

#define ASTRIDE 20                  // A smem row stride (floats): 80B, 16B-aligned, conflict-free
#define BSTRIDE 136                 // B smem row stride (floats): conflict-free frag reads
#define A_STAGE (BM * ASTRIDE)      // 2560 floats
#define B_STAGE (BK * BSTRIDE)      // 2176 floats

// ---------------- scratch (device globals: no allocations allowed) ----------
// NOTE: never passed as kernel arguments from host (host-side &g_x is the host
// shadow, silently writable via ATS on GB300!). Always referenced in device code.
__device__ float g_h[(size_t)NA * H_HID];
__device__ float g_o[(size_t)NA * D_IN];
__device__ int   g_counts[NE];
__device__ int   g_cursor[NE];
__device__ int   g_offsets[NE + 1];
__device__ int   g_bucket_tok[NA];
__device__ int   g_tok_pos[NA];
__device__ float g_tok_w[NA];
__device__ int2  g_tiles[MAX_TILES];
__device__ int   g_ntiles;

__device__ __forceinline__ float gelu_exact(float v) {
    return 0.5f * v * (1.0f + erff(v * 0.70710678118654752f));
}

// ---------------- 0: zero counters -------------------------------------------
__global__ void zero_kernel() {
    int i = threadIdx.x;
    if (i < NE) { g_counts[i] = 0; g_cursor[i] = 0; }
}

// ---------------- 1: router (one warp per token) -----------------------------
__global__ void router_kernel(const float* __restrict__ x,
                              const float* __restrict__ Wr,
                              const float* __restrict__ br) {
    int warp = (blockIdx.x * blockDim.x + threadIdx.x) >> 5;
    int lane = threadIdx.x & 31;
    if (warp >= T_TOK) return;

    const float* xr = x + (size_t)warp * D_IN;
    float acc[NE];
#pragma unroll
    for (int e = 0; e < NE; e++) acc[e] = 0.f;

    for (int d = lane; d < D_IN; d += 32) {
        float xv = xr[d];
        const float* wrow = Wr + d * NE;
#pragma unroll
        for (int e = 0; e < NE; e++) acc[e] += xv * wrow[e];
    }
#pragma unroll
    for (int e = 0; e < NE; e++) {
#pragma unroll
        for (int off = 16; off; off >>= 1)
            acc[e] += __shfl_xor_sync(0xffffffffu, acc[e], off);
    }

    if (lane == 0) {
        float lg[NE];
        float mx = -1e30f;
#pragma unroll
        for (int e = 0; e < NE; e++) { lg[e] = acc[e] + br[e]; mx = fmaxf(mx, lg[e]); }
#pragma unroll
        for (int e = 0; e < NE; e++) lg[e] = expf(lg[e] - mx);

        int   i0 = 0; float p0 = lg[0];
#pragma unroll
        for (int e = 1; e < NE; e++) if (lg[e] > p0) { p0 = lg[e]; i0 = e; }
        int   i1 = -1; float p1 = -1.f;
#pragma unroll
        for (int e = 0; e < NE; e++) if (e != i0 && lg[e] > p1) { p1 = lg[e]; i1 = e; }

        float inv = 1.f / (p0 + p1);
        g_tok_w[warp * 2 + 0] = p0 * inv;
        g_tok_w[warp * 2 + 1] = p1 * inv;
        g_tok_pos[warp * 2 + 0] = i0;   // expert idx for now
        g_tok_pos[warp * 2 + 1] = i1;
        atomicAdd(&g_counts[i0], 1);
        atomicAdd(&g_counts[i1], 1);
    }
}

// ---------------- 2: scan + tile worklist ------------------------------------
__global__ void scan_kernel() {
    if (threadIdx.x != 0) return;
    int off = 0;
    for (int e = 0; e < NE; e++) { g_offsets[e] = off; off += g_counts[e]; }
    g_offsets[NE] = off;
    int nt = 0;
    for (int e = 0; e < NE; e++)
        for (int r = 0; r < g_counts[e]; r += BM)
            g_tiles[nt++] = make_int2(e, g_offsets[e] + r);
    g_ntiles = nt;
}

// ---------------- 3: scatter assignments into expert buckets -----------------
__global__ void scatter_kernel() {
    int i = blockIdx.x * blockDim.x + threadIdx.x;
    if (i >= NA) return;
    int e   = g_tok_pos[i];
    int pos = g_offsets[e] + atomicAdd(&g_cursor[e], 1);
    g_bucket_tok[pos] = i >> 1;
    g_tok_pos[i]      = pos;
}

// ---------------- 4/5: tensor-core GEMM (tf32 mma.sync, static smem) ----------
// FIRST: A = gathered x rows, Out = g_h, GELU epilogue.
// !FIRST: A = g_h rows,       Out = g_o, bias-only epilogue.
template<int K, int N, bool FIRST>
__global__ __launch_bounds__(256) void mma_gemm(const float* __restrict__ Xarg,
                                                const float* __restrict__ Wbase,
                                                const float* __restrict__ bias) {
    int tile = blockIdx.y;
    if (tile >= g_ntiles) return;
    int e    = g_tiles[tile].x;
    int row0 = g_tiles[tile].y;
    int rows = min(BM, g_offsets[e + 1] - row0);
    int n0   = blockIdx.x * BN;

    const float* Abase = FIRST ? Xarg : (const float*)g_h;  // device-resolved
    float*       Out   = FIRST ? (float*)g_h : (float*)g_o; // device-resolved

    __shared__ float sA[2 * A_STAGE];   // 20.0 KB
    __shared__ float sB[2 * B_STAGE];   // 17.0 KB  -> 37.9 KB static
    uint32_t sA_u = (uint32_t)__cvta_generic_to_shared(sA);
    uint32_t sB_u = (uint32_t)__cvta_generic_to_shared(sB);

    const float* W = Wbase + (size_t)e * K * N;

    int tid  = threadIdx.x;
    int lane = tid & 31;
    int warp = tid >> 5;
    int mw = (warp >> 2) * 64;   // warp m-base within tile
    int nw = (warp & 3) * 32;    // warp n-base within tile
    int g  = lane >> 2;          // mma group id
    int tg = lane & 3;           // thread-in-group

    // ---- A load: 2 threads per row, 2x 16B chunks each (row = 16 floats) ----
    int lm  = tid >> 1;          // row 0..127
    int ac0 = (tid & 1) * 2;     // chunk base 0 or 2
    const float* aptr;
    int asz = 16;
    if (FIRST) {
        int tok = (lm < rows) ? g_bucket_tok[row0 + lm] : -1;
        aptr = Abase + (size_t)(tok < 0 ? 0 : tok) * K;
        if (tok < 0) asz = 0;
    } else {
        aptr = Abase + (size_t)(row0 + (lm < rows ? lm : 0)) * K;
        if (lm >= rows) asz = 0;
    }
    // ---- B load: 16 threads per k-row, 2x 16B chunks each (row = 128 floats) --
    int kb  = tid >> 4;          // k row 0..15
    int bc0 = (tid & 15) * 2;    // chunk base

    float acc[4][4][4] = {};

    const int KT = K / BK;
#define LOAD_STAGE(kt, s)                                                              \
    {                                                                                  \
        int k0 = (kt) * BK;                                                            \
        uint32_t ad = sA_u + ((s) * A_STAGE + lm * ASTRIDE) * 4;                       \
        const float* asrc = aptr + k0;                                                 \
        _Pragma("unroll")                                                              \
        for (int j = 0; j < 2; j++) {                                                  \
            int c = ac0 + j;                                                           \
            asm volatile("cp.async.cg.shared.global [%0], [%1], 16, %2;\n"             \
                         :: "r"(ad + c * 16), "l"(asrc + c * 4), "r"(asz));            \
        }                                                                              \
        uint32_t bd = sB_u + ((s) * B_STAGE + kb * BSTRIDE) * 4;                       \
        const float* bsrc = W + (size_t)(k0 + kb) * N + n0;                            \
        _Pragma("unroll")                                                              \
        for (int j = 0; j < 2; j++) {                                                  \
            int c = bc0 + j;                                                           \
            asm volatile("cp.async.cg.shared.global [%0], [%1], 16;\n"                 \
                         :: "r"(bd + c * 16), "l"(bsrc + c * 4));                      \
        }                                                                              \
        asm volatile("cp.async.commit_group;\n");                                      \
    }

    LOAD_STAGE(0, 0)
    for (int kt = 0; kt < KT; kt++) {
        int s = kt & 1;
        if (kt + 1 < KT) {
            LOAD_STAGE(kt + 1, s ^ 1)
            asm volatile("cp.async.wait_group 1;\n");
        } else {
            asm volatile("cp.async.wait_group 0;\n");
        }
        __syncthreads();

        const float* Ast = sA + s * A_STAGE;
        const float* Bst = sB + s * B_STAGE;
#pragma unroll
        for (int ks = 0; ks < 2; ks++) {
            // A frag (m16n8k8.tf32): a0=(r,k) a1=(r+8,k) a2=(r,k+4) a3=(r+8,k+4)
            int kA = ks * 8 + tg;
            uint32_t a[4][4];
#pragma unroll
            for (int mt = 0; mt < 4; mt++) {
                int r0_ = mw + mt * 16 + g;
                int r1_ = r0_ + 8;
                a[mt][0] = __float_as_uint(Ast[r0_ * ASTRIDE + kA]);
                a[mt][1] = __float_as_uint(Ast[r1_ * ASTRIDE + kA]);
                a[mt][2] = __float_as_uint(Ast[r0_ * ASTRIDE + kA + 4]);
                a[mt][3] = __float_as_uint(Ast[r1_ * ASTRIDE + kA + 4]);
            }
            // B frag: b0=(k,n) b1=(k+4,n), k=ks*8+tg, n=nw+nt*8+g
            uint32_t b[4][2];
            int kk = ks * 8 + tg;
#pragma unroll
            for (int nt = 0; nt < 4; nt++) {
                int nn = nw + nt * 8 + g;
                b[nt][0] = __float_as_uint(Bst[kk * BSTRIDE + nn]);
                b[nt][1] = __float_as_uint(Bst[(kk + 4) * BSTRIDE + nn]);
            }
#pragma unroll
            for (int mt = 0; mt < 4; mt++)
#pragma unroll
                for (int nt = 0; nt < 4; nt++) {
                    asm volatile(
                        "mma.sync.aligned.m16n8k8.row.col.f32.tf32.tf32.f32 "
                        "{%0,%1,%2,%3}, {%4,%5,%6,%7}, {%8,%9}, {%0,%1,%2,%3};\n"
                        : "+f"(acc[mt][nt][0]), "+f"(acc[mt][nt][1]),
                          "+f"(acc[mt][nt][2]), "+f"(acc[mt][nt][3])
                        : "r"(a[mt][0]), "r"(a[mt][1]), "r"(a[mt][2]), "r"(a[mt][3]),
                          "r"(b[nt][0]), "r"(b[nt][1]));
                }
        }
        __syncthreads();
    }
#undef LOAD_STAGE

    // ---- epilogue: bias (+GELU for FIRST), store ----
    const float* bv = bias + (size_t)e * N + n0;
#pragma unroll
    for (int nt = 0; nt < 4; nt++) {
        int col = nw + nt * 8 + tg * 2;
        float2 bb = *(const float2*)&bv[col];
#pragma unroll
        for (int mt = 0; mt < 4; mt++) {
            int lr = mw + mt * 16 + g;
#pragma unroll
            for (int h = 0; h < 2; h++) {
                int r = lr + h * 8;
                if (r < rows) {
                    float2 o;
                    o.x = acc[mt][nt][2 * h + 0] + bb.x;
                    o.y = acc[mt][nt][2 * h + 1] + bb.y;
                    if (FIRST) { o.x = gelu_exact(o.x); o.y = gelu_exact(o.y); }
                    *(float2*)&Out[(size_t)(row0 + r) * N + n0 + col] = o;
                }
            }
        }
    }
}

// ---------------- 6: combine + residual (deterministic gather) ---------------
__global__ void combine_kernel(const float* __restrict__ x, float* __restrict__ out) {
    int t = blockIdx.x;
    int d = threadIdx.x * 4;
    float w0 = g_tok_w[2 * t + 0], w1 = g_tok_w[2 * t + 1];
    int   p0 = g_tok_pos[2 * t + 0], p1 = g_tok_pos[2 * t + 1];
    float4 xv = *(const float4*)&x[(size_t)t * D_IN + d];
    float4 o0 = *(const float4*)&g_o[(size_t)p0 * D_IN + d];
    float4 o1 = *(const float4*)&g_o[(size_t)p1 * D_IN + d];
    float4 r;
    r.x = xv.x + w0 * o0.x + w1 * o1.x;
    r.y = xv.y + w0 * o0.y + w1 * o1.y;
    r.z = xv.z + w0 * o0.z + w1 * o1.z;
    r.w = xv.w + w0 * o0.w + w1 * o1.w;
    *(float4*)&out[(size_t)t * D_IN + d] = r;
}

// ---------------- launch ------------------------------------------------------
extern "C" void kernel_launch(void* const* d_in, const int* in_sizes, int n_in,
                              void* d_out, int out_size) {
    const float* x  = (const float*)d_in[0];
    const float* Wr = (const float*)d_in[1];
    const float* br = (const float*)d_in[2];
    const float* W1 = (const float*)d_in[3];
    const float* b1 = (const float*)d_in[4];
    const float* W2 = (const float*)d_in[5];
    const float* b2 = (const float*)d_in[6];
    float* out = (float*)d_out;

    zero_kernel<<<1, 32>>>();
    router_kernel<<<T_TOK / 8, 256>>>(x, Wr, br);
    scan_kernel<<<1, 32>>>();
    scatter_kernel<<<(NA + 255) / 256, 256>>>();
    mma_gemm<D_IN, H_HID, true><<<dim3(H_HID / BN, MAX_TILES), 256>>>(x, W1, b1);
    mma_gemm<H_HID, D_IN, false><<<dim3(D_IN / BN, MAX_TILES), 256>>>(nullptr, W2, b2);
    combine_kernel<<<T_TOK, 128>>>(x, out);
}